// round 10
// baseline (speedup 1.0000x reference)
#include <cuda_runtime.h>
#include <cuda_bf16.h>
#include <cstdint>

#define DFEAT 256
#define NCOLS 512
#define MAXN  100000

// Scratch: P = [u | v] per node, bf16, 16B-aligned. g_W2 = W1 rearranged,
// k-pair interleaved. g_flags[mb] counts completed N-tiles (4 = row-block ready).
__device__ __align__(16) __nv_bfloat16 g_P[(size_t)MAXN * NCOLS];
__device__ __align__(16) __nv_bfloat16 g_W2[(DFEAT / 2) * NCOLS * 2];
__device__ int g_flags[1024];

// Wcat[k][j] = W1[k][j] (j<256) | W1[256+k][j-256]; pair-interleaved bf16.
// Also zeroes the readiness flags (runs before fused kernel, same stream).
__global__ void prep_w(const float* __restrict__ W1) {
    int idx = blockIdx.x * blockDim.x + threadIdx.x;
    if (idx < 1024) g_flags[idx] = 0;
    if (idx >= NCOLS * DFEAT) return;
    int j = idx >> 8;          // output col 0..511
    int k = idx & 255;         // input  dim 0..255
    float w = (j < DFEAT) ? W1[k * DFEAT + j]
                          : W1[(DFEAT + k) * DFEAT + (j - DFEAT)];
    g_W2[(size_t)(k >> 1) * (NCOLS * 2) + j * 2 + (k & 1)] = __float2bfloat16(w);
}

#define BM 128
#define BN 128
#define BK 32
#define ASTR 36
#define BSTR2 136
#define A_STAGE (BM * ASTR)
#define B_STAGE ((BK / 2) * BSTR2)
#define NSTAGE 3
#define SMEM_FLOATS (NSTAGE * (A_STAGE + B_STAGE))   // 81408 B

__device__ __forceinline__ void cp16(void* dst_s, const void* src_g, bool pred) {
    uint32_t d = (uint32_t)__cvta_generic_to_shared(dst_s);
    int sz = pred ? 16 : 0;
    asm volatile("cp.async.ca.shared.global [%0], [%1], 16, %2;"
                 :: "r"(d), "l"(src_g), "r"(sz));
}

// Acquire-spin until row-block mb's 4 N-tiles are written.
__device__ __forceinline__ void wait_rb(int mb) {
    int f;
    asm volatile("ld.global.acquire.gpu.b32 %0, [%1];"
                 : "=r"(f) : "l"(g_flags + mb) : "memory");
    while (f < 4) {
        __nanosleep(400);
        asm volatile("ld.global.acquire.gpu.b32 %0, [%1];"
                     : "=r"(f) : "l"(g_flags + mb) : "memory");
    }
}

__device__ __forceinline__ float edge_dot(uint4 uu, uint4 vv,
                                          const float* bb, const float* ww) {
    float acc = 0.f;
    const uint32_t* up = &uu.x;
    const uint32_t* vp = &vv.x;
    #pragma unroll
    for (int q = 0; q < 4; q++) {
        float2 uf = __bfloat1622float2(*(const __nv_bfloat162*)&up[q]);
        float2 vf = __bfloat1622float2(*(const __nv_bfloat162*)&vp[q]);
        float t;
        t = uf.x + vf.x + bb[2 * q];     if (t > 0.f) acc += t * ww[2 * q];
        t = uf.y + vf.y + bb[2 * q + 1]; if (t > 0.f) acc += t * ww[2 * q + 1];
    }
    return acc;
}

// Fused: blocks [0,NG) = GEMM tiles (R9 code), blocks [NG,..) = edge pass
// gated on per-row-block flags. 2 CTAs/SM so edge overlaps GEMM.
__global__ __launch_bounds__(256, 2) void fused(
        const float* __restrict__ h, int M, int NG,
        const int* __restrict__ src, const int* __restrict__ dst,
        const float* __restrict__ b1, const float* __restrict__ W2,
        const float* __restrict__ b2, float* __restrict__ out, int E) {
    extern __shared__ __align__(16) float smem[];
    int tid  = threadIdx.x;
    int lane = tid & 31, warp = tid >> 5;

    if ((int)blockIdx.x < NG) {
        // ------------------------- GEMM role (R9 verbatim) -------------------
        float*    As = smem;
        uint32_t* Bs = (uint32_t*)(smem + NSTAGE * A_STAGE);
        int wm = (warp >> 2) * 64;
        int wn = (warp & 3) * 32;
        int g  = lane >> 2, tg = lane & 3;
        int mTile   = blockIdx.x >> 2;
        int rowBase = mTile * BM;
        int nBase   = (blockIdx.x & 3) * BN;

        float c[4][4][4];
        #pragma unroll
        for (int i = 0; i < 4; i++)
            #pragma unroll
            for (int j = 0; j < 4; j++)
                #pragma unroll
                for (int q = 0; q < 4; q++) c[i][j][q] = 0.f;

        int ar[4], ac[4];
        #pragma unroll
        for (int i = 0; i < 4; i++) {
            int idx = tid + 256 * i;
            ar[i] = idx >> 3;
            ac[i] = (idx & 7) << 2;
        }
        int br[2], bc[2];
        #pragma unroll
        for (int i = 0; i < 2; i++) {
            int idx = tid + 256 * i;
            br[i] = idx >> 5;
            bc[i] = (idx & 31) << 2;
        }

        auto load_stage = [&](int st, int k0) {
            float*    a_s = As + st * A_STAGE;
            uint32_t* b_s = Bs + st * B_STAGE;
            #pragma unroll
            for (int i = 0; i < 4; i++) {
                int grow = rowBase + ar[i];
                cp16(a_s + ar[i] * ASTR + ac[i],
                     h + (size_t)grow * DFEAT + k0 + ac[i], grow < M);
            }
            int k2base = k0 >> 1;
            #pragma unroll
            for (int i = 0; i < 2; i++) {
                cp16(b_s + br[i] * BSTR2 + bc[i],
                     g_W2 + (size_t)(k2base + br[i]) * (NCOLS * 2) + nBase * 2 + bc[i] * 2,
                     true);
            }
            asm volatile("cp.async.commit_group;");
        };

        load_stage(0, 0);
        load_stage(1, BK);

        for (int ck = 0; ck < DFEAT / BK; ck++) {
            if (ck + 1 < DFEAT / BK) asm volatile("cp.async.wait_group 1;");
            else                     asm volatile("cp.async.wait_group 0;");
            __syncthreads();

            const float*    a_s = As + (ck % NSTAGE) * A_STAGE;
            const uint32_t* b_s = Bs + (ck % NSTAGE) * B_STAGE;

            #pragma unroll
            for (int kk = 0; kk < BK; kk += 16) {
                uint32_t a[4][4];
                #pragma unroll
                for (int mt = 0; mt < 4; mt++) {
                    const float* ap = a_s + (wm + mt * 16) * ASTR + kk + 2 * tg;
                    float2 f0 = *(const float2*)(ap + g * ASTR);
                    float2 f1 = *(const float2*)(ap + (g + 8) * ASTR);
                    float2 f2 = *(const float2*)(ap + g * ASTR + 8);
                    float2 f3 = *(const float2*)(ap + (g + 8) * ASTR + 8);
                    asm("cvt.rn.bf16x2.f32 %0, %1, %2;" : "=r"(a[mt][0]) : "f"(f0.y), "f"(f0.x));
                    asm("cvt.rn.bf16x2.f32 %0, %1, %2;" : "=r"(a[mt][1]) : "f"(f1.y), "f"(f1.x));
                    asm("cvt.rn.bf16x2.f32 %0, %1, %2;" : "=r"(a[mt][2]) : "f"(f2.y), "f"(f2.x));
                    asm("cvt.rn.bf16x2.f32 %0, %1, %2;" : "=r"(a[mt][3]) : "f"(f3.y), "f"(f3.x));
                }
                uint32_t b[4][2];
                #pragma unroll
                for (int nt = 0; nt < 4; nt++) {
                    const uint32_t* bp = b_s + (kk >> 1) * BSTR2 + wn + nt * 8 + g;
                    b[nt][0] = bp[tg * BSTR2];
                    b[nt][1] = bp[(tg + 4) * BSTR2];
                }
                #pragma unroll
                for (int mt = 0; mt < 4; mt++)
                    #pragma unroll
                    for (int nt = 0; nt < 4; nt++) {
                        asm volatile(
                            "mma.sync.aligned.m16n8k16.row.col.f32.bf16.bf16.f32 "
                            "{%0,%1,%2,%3}, {%4,%5,%6,%7}, {%8,%9}, {%0,%1,%2,%3};"
                            : "+f"(c[mt][nt][0]), "+f"(c[mt][nt][1]),
                              "+f"(c[mt][nt][2]), "+f"(c[mt][nt][3])
                            : "r"(a[mt][0]), "r"(a[mt][1]), "r"(a[mt][2]), "r"(a[mt][3]),
                              "r"(b[nt][0]), "r"(b[nt][1]));
                    }
            }
            __syncthreads();
            if (ck + 2 < DFEAT / BK) load_stage((ck + 2) % NSTAGE, (ck + 2) * BK);
        }

        #pragma unroll
        for (int mt = 0; mt < 4; mt++) {
            int row0 = rowBase + wm + mt * 16 + g;
            #pragma unroll
            for (int nt = 0; nt < 4; nt++) {
                int col = nBase + wn + nt * 8 + 2 * tg;
                if (row0 < M)
                    *(__nv_bfloat162*)(g_P + (size_t)row0 * NCOLS + col) =
                        __float22bfloat162_rn(make_float2(c[mt][nt][0], c[mt][nt][1]));
                if (row0 + 8 < M)
                    *(__nv_bfloat162*)(g_P + (size_t)(row0 + 8) * NCOLS + col) =
                        __float22bfloat162_rn(make_float2(c[mt][nt][2], c[mt][nt][3]));
            }
        }
        // Release this tile: P stores -> fence -> block-wide sync -> count.
        __threadfence();
        __syncthreads();
        if (tid == 0) atomicAdd(&g_flags[mTile], 1);
    } else {
        // ------------------------- edge role (R9 2-deep + flag gating) -------
        int ebid = blockIdx.x - NG;
        int gwarp = ebid * 8 + warp;
        int nwarps = ((int)gridDim.x - NG) * 8;

        float bb[8], ww[8];
        #pragma unroll
        for (int i = 0; i < 8; i++) {
            bb[i] = __ldg(b1 + lane * 8 + i);
            ww[i] = __ldg(W2 + lane * 8 + i);
        }
        float bias2 = __ldg(b2);

        const __nv_bfloat16* P = g_P;
        for (int e = gwarp; e < E; e += 2 * nwarps) {
            int e2 = e + nwarps;
            bool have2 = e2 < E;
            int s0 = src[e], d0 = dst[e];
            int s1 = have2 ? src[e2] : 0;
            int d1 = have2 ? dst[e2] : 0;

            wait_rb(s0 >> 7); wait_rb(d0 >> 7);
            wait_rb(s1 >> 7); wait_rb(d1 >> 7);

            uint4 u0 = *(const uint4*)(P + (size_t)s0 * NCOLS + lane * 8);
            uint4 v0 = *(const uint4*)(P + (size_t)d0 * NCOLS + DFEAT + lane * 8);
            uint4 u1 = *(const uint4*)(P + (size_t)s1 * NCOLS + lane * 8);
            uint4 v1 = *(const uint4*)(P + (size_t)d1 * NCOLS + DFEAT + lane * 8);

            float a0 = edge_dot(u0, v0, bb, ww);
            float a1 = edge_dot(u1, v1, bb, ww);
            #pragma unroll
            for (int o = 16; o; o >>= 1) {
                a0 += __shfl_xor_sync(0xffffffffu, a0, o);
                a1 += __shfl_xor_sync(0xffffffffu, a1, o);
            }
            if (lane == 0) {
                out[e] = 1.f / (1.f + __expf(-(a0 + bias2)));
                if (have2) out[e2] = 1.f / (1.f + __expf(-(a1 + bias2)));
            }
        }
    }
}

extern "C" void kernel_launch(void* const* d_in, const int* in_sizes, int n_in,
                              void* d_out, int out_size) {
    const float* h   = (const float*)d_in[0];
    const int*   src = (const int*)d_in[1];
    const int*   dst = (const int*)d_in[2];
    const float* W1  = (const float*)d_in[3];
    const float* b1  = (const float*)d_in[4];
    const float* W2  = (const float*)d_in[5];
    const float* b2  = (const float*)d_in[6];
    float* out = (float*)d_out;

    int M = in_sizes[0] / DFEAT;
    int E = in_sizes[1];
    int MB = (M + BM - 1) / BM;
    int NG = 4 * MB;             // GEMM blocks (x-fastest N within row-block)
    int NEB = 2368;              // edge blocks

    prep_w<<<(NCOLS * DFEAT + 255) / 256, 256>>>(W1);

    int smem_bytes = SMEM_FLOATS * (int)sizeof(float);   // 81408 B
    cudaFuncSetAttribute(fused, cudaFuncAttributeMaxDynamicSharedMemorySize,
                         smem_bytes);
    fused<<<NG + NEB, 256, smem_bytes>>>(h, M, NG, src, dst, b1, W2, b2, out, E);
}

// round 11
// speedup vs baseline: 1.7697x; 1.7697x over previous
#include <cuda_runtime.h>
#include <cuda_bf16.h>
#include <cstdint>

#define DFEAT 256
#define NCOLS 512
#define MAXN  100000

// Scratch: P = [u | v] per node, bf16, 16B-aligned (uint4 reads).
// g_W2 = W1 rearranged, k-pair interleaved: word (k/2, n) = {W[k][n], W[k+1][n]}.
__device__ __align__(16) __nv_bfloat16 g_P[(size_t)MAXN * NCOLS];
__device__ __align__(16) __nv_bfloat16 g_W2[(DFEAT / 2) * NCOLS * 2];

// Wcat[k][j] = W1[k][j] (j<256) | W1[256+k][j-256]; stored pair-interleaved bf16.
__global__ void prep_w(const float* __restrict__ W1) {
    int idx = blockIdx.x * blockDim.x + threadIdx.x;
    if (idx >= NCOLS * DFEAT) return;
    int j = idx >> 8;          // output col 0..511
    int k = idx & 255;         // input  dim 0..255
    float w = (j < DFEAT) ? W1[k * DFEAT + j]
                          : W1[(DFEAT + k) * DFEAT + (j - DFEAT)];
    g_W2[(size_t)(k >> 1) * (NCOLS * 2) + j * 2 + (k & 1)] = __float2bfloat16(w);
}

// ----- bf16 m16n8k16 GEMM, 3-stage cp.async, 2 CTAs/SM (R9 + occupancy) -----
#define BM 128
#define BN 128
#define BK 32
#define ASTR 36                    // A row stride in floats (144B)
#define BSTR2 136                  // B row stride in uint32 (544B)
#define A_STAGE (BM * ASTR)
#define B_STAGE ((BK / 2) * BSTR2)
#define NSTAGE 3
#define SMEM_FLOATS (NSTAGE * (A_STAGE + B_STAGE))   // 81408 B

__device__ __forceinline__ void cp16(void* dst_s, const void* src_g, bool pred) {
    uint32_t d = (uint32_t)__cvta_generic_to_shared(dst_s);
    int sz = pred ? 16 : 0;   // 0 => zero-fill
    asm volatile("cp.async.ca.shared.global [%0], [%1], 16, %2;"
                 :: "r"(d), "l"(src_g), "r"(sz));
}

__global__ __launch_bounds__(256, 2) void gemm_bf16(const float* __restrict__ h, int M) {
    extern __shared__ __align__(16) float smem[];
    float*    As = smem;                                  // [NSTAGE][A_STAGE]
    uint32_t* Bs = (uint32_t*)(smem + NSTAGE * A_STAGE);  // [NSTAGE][B_STAGE]

    int tid  = threadIdx.x;
    int lane = tid & 31, warp = tid >> 5;
    int wm = (warp >> 2) * 64;         // warp grid 2(m) x 4(n), warp tile 64x32
    int wn = (warp & 3) * 32;
    int g  = lane >> 2, tg = lane & 3;
    int rowBase = blockIdx.y * BM;
    int nBase   = blockIdx.x * BN;

    float c[4][4][4];
    #pragma unroll
    for (int i = 0; i < 4; i++)
        #pragma unroll
        for (int j = 0; j < 4; j++)
            #pragma unroll
            for (int q = 0; q < 4; q++) c[i][j][q] = 0.f;

    // A-load mapping: 1024 x 16B slots, 4/thread
    int ar[4], ac[4];
    #pragma unroll
    for (int i = 0; i < 4; i++) {
        int idx = tid + 256 * i;
        ar[i] = idx >> 3;           // row 0..127
        ac[i] = (idx & 7) << 2;     // col 0..28 step 4 (floats)
    }
    // B-load mapping: 512 x 16B slots, 2/thread (16 rows x 128 uint32)
    int br[2], bc[2];
    #pragma unroll
    for (int i = 0; i < 2; i++) {
        int idx = tid + 256 * i;
        br[i] = idx >> 5;           // k2 row 0..15
        bc[i] = (idx & 31) << 2;    // word col 0..124 step 4
    }

    auto load_stage = [&](int st, int k0) {
        float*    a_s = As + st * A_STAGE;
        uint32_t* b_s = Bs + st * B_STAGE;
        #pragma unroll
        for (int i = 0; i < 4; i++) {
            int grow = rowBase + ar[i];
            cp16(a_s + ar[i] * ASTR + ac[i],
                 h + (size_t)grow * DFEAT + k0 + ac[i], grow < M);
        }
        int k2base = k0 >> 1;
        #pragma unroll
        for (int i = 0; i < 2; i++) {
            cp16(b_s + br[i] * BSTR2 + bc[i],
                 g_W2 + (size_t)(k2base + br[i]) * (NCOLS * 2) + nBase * 2 + bc[i] * 2,
                 true);
        }
        asm volatile("cp.async.commit_group;");
    };

    load_stage(0, 0);
    load_stage(1, BK);

    for (int ck = 0; ck < DFEAT / BK; ck++) {          // 8 chunks
        if (ck + 1 < DFEAT / BK) asm volatile("cp.async.wait_group 1;");
        else                     asm volatile("cp.async.wait_group 0;");
        __syncthreads();

        const float*    a_s = As + (ck % NSTAGE) * A_STAGE;
        const uint32_t* b_s = Bs + (ck % NSTAGE) * B_STAGE;

        #pragma unroll
        for (int kk = 0; kk < BK; kk += 16) {
            // A frags (m16n8k16): a0 (g,2tg) a1 (g+8,2tg) a2 (g,2tg+8) a3 (g+8,2tg+8)
            uint32_t a[4][4];
            #pragma unroll
            for (int mt = 0; mt < 4; mt++) {
                const float* ap = a_s + (wm + mt * 16) * ASTR + kk + 2 * tg;
                float2 f0 = *(const float2*)(ap + g * ASTR);
                float2 f1 = *(const float2*)(ap + (g + 8) * ASTR);
                float2 f2 = *(const float2*)(ap + g * ASTR + 8);
                float2 f3 = *(const float2*)(ap + (g + 8) * ASTR + 8);
                asm("cvt.rn.bf16x2.f32 %0, %1, %2;" : "=r"(a[mt][0]) : "f"(f0.y), "f"(f0.x));
                asm("cvt.rn.bf16x2.f32 %0, %1, %2;" : "=r"(a[mt][1]) : "f"(f1.y), "f"(f1.x));
                asm("cvt.rn.bf16x2.f32 %0, %1, %2;" : "=r"(a[mt][2]) : "f"(f2.y), "f"(f2.x));
                asm("cvt.rn.bf16x2.f32 %0, %1, %2;" : "=r"(a[mt][3]) : "f"(f3.y), "f"(f3.x));
            }
            // B frags: b0 = pair row (kk/2 + tg), b1 = pair row (kk/2 + tg + 4), col n
            uint32_t b[4][2];
            #pragma unroll
            for (int nt = 0; nt < 4; nt++) {
                const uint32_t* bp = b_s + (kk >> 1) * BSTR2 + wn + nt * 8 + g;
                b[nt][0] = bp[tg * BSTR2];
                b[nt][1] = bp[(tg + 4) * BSTR2];
            }
            #pragma unroll
            for (int mt = 0; mt < 4; mt++)
                #pragma unroll
                for (int nt = 0; nt < 4; nt++) {
                    asm volatile(
                        "mma.sync.aligned.m16n8k16.row.col.f32.bf16.bf16.f32 "
                        "{%0,%1,%2,%3}, {%4,%5,%6,%7}, {%8,%9}, {%0,%1,%2,%3};"
                        : "+f"(c[mt][nt][0]), "+f"(c[mt][nt][1]),
                          "+f"(c[mt][nt][2]), "+f"(c[mt][nt][3])
                        : "r"(a[mt][0]), "r"(a[mt][1]), "r"(a[mt][2]), "r"(a[mt][3]),
                          "r"(b[nt][0]), "r"(b[nt][1]));
                }
        }
        __syncthreads();

        if (ck + 2 < DFEAT / BK) load_stage((ck + 2) % NSTAGE, (ck + 2) * BK);
    }

    // Epilogue -> bf16 P. C frag: c0 (g,2tg) c1 (g,2tg+1) c2 (g+8,2tg) c3 (g+8,2tg+1)
    #pragma unroll
    for (int mt = 0; mt < 4; mt++) {
        int row0 = rowBase + wm + mt * 16 + g;
        #pragma unroll
        for (int nt = 0; nt < 4; nt++) {
            int col = nBase + wn + nt * 8 + 2 * tg;
            if (row0 < M)
                *(__nv_bfloat162*)(g_P + (size_t)row0 * NCOLS + col) =
                    __float22bfloat162_rn(make_float2(c[mt][nt][0], c[mt][nt][1]));
            if (row0 + 8 < M)
                *(__nv_bfloat162*)(g_P + (size_t)(row0 + 8) * NCOLS + col) =
                    __float22bfloat162_rn(make_float2(c[mt][nt][2], c[mt][nt][3]));
        }
    }
}

// ------------- edge pass (proven): warp/edge, 2 edges in flight --------------
__device__ __forceinline__ float edge_dot(uint4 uu, uint4 vv,
                                          const float* bb, const float* ww) {
    float acc = 0.f;
    const uint32_t* up = &uu.x;
    const uint32_t* vp = &vv.x;
    #pragma unroll
    for (int q = 0; q < 4; q++) {
        float2 uf = __bfloat1622float2(*(const __nv_bfloat162*)&up[q]);
        float2 vf = __bfloat1622float2(*(const __nv_bfloat162*)&vp[q]);
        float t;
        t = uf.x + vf.x + bb[2 * q];     if (t > 0.f) acc += t * ww[2 * q];
        t = uf.y + vf.y + bb[2 * q + 1]; if (t > 0.f) acc += t * ww[2 * q + 1];
    }
    return acc;
}

__global__ __launch_bounds__(256) void edge_mlp(
        const int* __restrict__ src, const int* __restrict__ dst,
        const float* __restrict__ b1, const float* __restrict__ W2,
        const float* __restrict__ b2, float* __restrict__ out, int E) {
    int tid = threadIdx.x;
    int lane = tid & 31;
    int gwarp = blockIdx.x * 8 + (tid >> 5);
    int nwarps = gridDim.x * 8;

    float bb[8], ww[8];
    #pragma unroll
    for (int i = 0; i < 8; i++) {
        bb[i] = __ldg(b1 + lane * 8 + i);
        ww[i] = __ldg(W2 + lane * 8 + i);
    }
    float bias2 = __ldg(b2);

    const __nv_bfloat16* P = g_P;
    for (int e = gwarp; e < E; e += 2 * nwarps) {
        int e2 = e + nwarps;
        bool have2 = e2 < E;
        int s0 = src[e], d0 = dst[e];
        int s1 = have2 ? src[e2] : 0;
        int d1 = have2 ? dst[e2] : 0;

        uint4 u0 = *(const uint4*)(P + (size_t)s0 * NCOLS + lane * 8);
        uint4 v0 = *(const uint4*)(P + (size_t)d0 * NCOLS + DFEAT + lane * 8);
        uint4 u1 = *(const uint4*)(P + (size_t)s1 * NCOLS + lane * 8);
        uint4 v1 = *(const uint4*)(P + (size_t)d1 * NCOLS + DFEAT + lane * 8);

        float a0 = edge_dot(u0, v0, bb, ww);
        float a1 = edge_dot(u1, v1, bb, ww);
        #pragma unroll
        for (int o = 16; o; o >>= 1) {
            a0 += __shfl_xor_sync(0xffffffffu, a0, o);
            a1 += __shfl_xor_sync(0xffffffffu, a1, o);
        }
        if (lane == 0) {
            out[e] = 1.f / (1.f + __expf(-(a0 + bias2)));
            if (have2) out[e2] = 1.f / (1.f + __expf(-(a1 + bias2)));
        }
    }
}

extern "C" void kernel_launch(void* const* d_in, const int* in_sizes, int n_in,
                              void* d_out, int out_size) {
    const float* h   = (const float*)d_in[0];
    const int*   src = (const int*)d_in[1];
    const int*   dst = (const int*)d_in[2];
    const float* W1  = (const float*)d_in[3];
    const float* b1  = (const float*)d_in[4];
    const float* W2  = (const float*)d_in[5];
    const float* b2  = (const float*)d_in[6];
    float* out = (float*)d_out;

    int M = in_sizes[0] / DFEAT;
    int E = in_sizes[1];

    prep_w<<<(NCOLS * DFEAT + 255) / 256, 256>>>(W1);

    int smem_bytes = SMEM_FLOATS * (int)sizeof(float);   // 81408 B
    cudaFuncSetAttribute(gemm_bf16, cudaFuncAttributeMaxDynamicSharedMemorySize,
                         smem_bytes);
    dim3 gg(NCOLS / BN, (M + BM - 1) / BM);   // x-fastest => A reuse in L2
    gemm_bf16<<<gg, 256, smem_bytes>>>(h, M);

    edge_mlp<<<2368, 256>>>(src, dst, b1, W2, b2, out, E);
}

// round 12
// speedup vs baseline: 2.1671x; 1.2246x over previous
#include <cuda_runtime.h>
#include <cuda_bf16.h>
#include <cstdint>

#define DFEAT 256
#define NCOLS 512
#define MAXN  100000

// Scratch: P = [u | v] per node, bf16, 16B-aligned (uint4 reads).
// g_Hb = h converted to bf16 [M x 256]. g_W2 = W1 rearranged, k-pair interleaved.
__device__ __align__(16) __nv_bfloat16 g_P[(size_t)MAXN * NCOLS];
__device__ __align__(16) __nv_bfloat16 g_Hb[(size_t)MAXN * DFEAT];
__device__ __align__(16) __nv_bfloat16 g_W2[(DFEAT / 2) * NCOLS * 2];

// Wcat[k][j] = W1[k][j] (j<256) | W1[256+k][j-256]; stored pair-interleaved bf16.
__global__ void prep_w(const float* __restrict__ W1) {
    int idx = blockIdx.x * blockDim.x + threadIdx.x;
    if (idx >= NCOLS * DFEAT) return;
    int j = idx >> 8;          // output col 0..511
    int k = idx & 255;         // input  dim 0..255
    float w = (j < DFEAT) ? W1[k * DFEAT + j]
                          : W1[(DFEAT + k) * DFEAT + (j - DFEAT)];
    g_W2[(size_t)(k >> 1) * (NCOLS * 2) + j * 2 + (k & 1)] = __float2bfloat16(w);
}

// h (fp32) -> g_Hb (bf16), 8 elements per thread, pure streaming.
__global__ void prep_h(const float* __restrict__ h, int M) {
    size_t i8 = (size_t)(blockIdx.x * blockDim.x + threadIdx.x);
    size_t total = (size_t)M * DFEAT / 8;
    if (i8 >= total) return;
    const float4* src = (const float4*)h + i8 * 2;
    float4 f0 = src[0], f1 = src[1];
    uint4 o;
    asm("cvt.rn.bf16x2.f32 %0, %1, %2;" : "=r"(o.x) : "f"(f0.y), "f"(f0.x));
    asm("cvt.rn.bf16x2.f32 %0, %1, %2;" : "=r"(o.y) : "f"(f0.w), "f"(f0.z));
    asm("cvt.rn.bf16x2.f32 %0, %1, %2;" : "=r"(o.z) : "f"(f1.y), "f"(f1.x));
    asm("cvt.rn.bf16x2.f32 %0, %1, %2;" : "=r"(o.w) : "f"(f1.w), "f"(f1.z));
    ((uint4*)g_Hb)[i8] = o;
}

// ----- bf16 m16n8k16 GEMM, 3-stage cp.async, 2 CTAs/SM, bf16 A path -----
#define BM 128
#define BN 128
#define BK 32
#define ABST 40                    // A row stride in bf16 (80B) - conflict-free LDS.32
#define BSTR2 136                  // B row stride in uint32 (544B)
#define A_STAGE_H (BM * ABST)      // bf16 units per A stage (5120 -> 10240B)
#define B_STAGE (BK / 2 * BSTR2)   // uint32 words per B stage (2176 -> 8704B)
#define NSTAGE 3
#define SMEM_BYTES (NSTAGE * (A_STAGE_H * 2 + B_STAGE * 4))   // 56832 B

__device__ __forceinline__ void cp16(void* dst_s, const void* src_g, bool pred) {
    uint32_t d = (uint32_t)__cvta_generic_to_shared(dst_s);
    int sz = pred ? 16 : 0;   // 0 => zero-fill
    asm volatile("cp.async.ca.shared.global [%0], [%1], 16, %2;"
                 :: "r"(d), "l"(src_g), "r"(sz));
}

__global__ __launch_bounds__(256, 2) void gemm_bf16(int M) {
    extern __shared__ __align__(16) char smem[];
    __nv_bfloat16* As = (__nv_bfloat16*)smem;                      // [NSTAGE][A_STAGE_H]
    uint32_t*      Bs = (uint32_t*)(smem + NSTAGE * A_STAGE_H * 2);// [NSTAGE][B_STAGE]

    int tid  = threadIdx.x;
    int lane = tid & 31, warp = tid >> 5;
    int wm = (warp >> 2) * 64;         // warp grid 2(m) x 4(n), warp tile 64x32
    int wn = (warp & 3) * 32;
    int g  = lane >> 2, tg = lane & 3;
    int rowBase = blockIdx.y * BM;
    int nBase   = blockIdx.x * BN;

    float c[4][4][4];
    #pragma unroll
    for (int i = 0; i < 4; i++)
        #pragma unroll
        for (int j = 0; j < 4; j++)
            #pragma unroll
            for (int q = 0; q < 4; q++) c[i][j][q] = 0.f;

    // A-load mapping: 128 rows x 64B = 512 x 16B slots, 2/thread
    int ar[2], ac[2];
    #pragma unroll
    for (int i = 0; i < 2; i++) {
        int idx = tid + 256 * i;
        ar[i] = idx >> 2;           // row 0..127
        ac[i] = (idx & 3) << 3;     // col 0..24 step 8 (bf16 units)
    }
    // B-load mapping: 512 x 16B slots, 2/thread (16 rows x 128 uint32)
    int br[2], bc[2];
    #pragma unroll
    for (int i = 0; i < 2; i++) {
        int idx = tid + 256 * i;
        br[i] = idx >> 5;           // k2 row 0..15
        bc[i] = (idx & 31) << 2;    // word col 0..124 step 4
    }

    auto load_stage = [&](int st, int k0) {
        __nv_bfloat16* a_s = As + st * A_STAGE_H;
        uint32_t*      b_s = Bs + st * B_STAGE;
        #pragma unroll
        for (int i = 0; i < 2; i++) {
            int grow = rowBase + ar[i];
            cp16(a_s + ar[i] * ABST + ac[i],
                 g_Hb + (size_t)grow * DFEAT + k0 + ac[i], grow < M);
        }
        int k2base = k0 >> 1;
        #pragma unroll
        for (int i = 0; i < 2; i++) {
            cp16(b_s + br[i] * BSTR2 + bc[i],
                 g_W2 + (size_t)(k2base + br[i]) * (NCOLS * 2) + nBase * 2 + bc[i] * 2,
                 true);
        }
        asm volatile("cp.async.commit_group;");
    };

    load_stage(0, 0);
    load_stage(1, BK);

    for (int ck = 0; ck < DFEAT / BK; ck++) {          // 8 chunks
        if (ck + 1 < DFEAT / BK) asm volatile("cp.async.wait_group 1;");
        else                     asm volatile("cp.async.wait_group 0;");
        __syncthreads();

        const __nv_bfloat16* a_s = As + (ck % NSTAGE) * A_STAGE_H;
        const uint32_t*      b_s = Bs + (ck % NSTAGE) * B_STAGE;

        #pragma unroll
        for (int kk = 0; kk < BK; kk += 16) {
            // A frags (m16n8k16): a0 (g,2tg) a1 (g+8,2tg) a2 (g,2tg+8) a3 (g+8,2tg+8)
            uint32_t a[4][4];
            #pragma unroll
            for (int mt = 0; mt < 4; mt++) {
                const __nv_bfloat16* ap = a_s + (wm + mt * 16) * ABST + kk + 2 * tg;
                a[mt][0] = *(const uint32_t*)(ap + g * ABST);
                a[mt][1] = *(const uint32_t*)(ap + (g + 8) * ABST);
                a[mt][2] = *(const uint32_t*)(ap + g * ABST + 8);
                a[mt][3] = *(const uint32_t*)(ap + (g + 8) * ABST + 8);
            }
            // B frags: b0 = pair row (kk/2 + tg), b1 = pair row (kk/2 + tg + 4), col n
            uint32_t b[4][2];
            #pragma unroll
            for (int nt = 0; nt < 4; nt++) {
                const uint32_t* bp = b_s + (kk >> 1) * BSTR2 + wn + nt * 8 + g;
                b[nt][0] = bp[tg * BSTR2];
                b[nt][1] = bp[(tg + 4) * BSTR2];
            }
            #pragma unroll
            for (int mt = 0; mt < 4; mt++)
                #pragma unroll
                for (int nt = 0; nt < 4; nt++) {
                    asm volatile(
                        "mma.sync.aligned.m16n8k16.row.col.f32.bf16.bf16.f32 "
                        "{%0,%1,%2,%3}, {%4,%5,%6,%7}, {%8,%9}, {%0,%1,%2,%3};"
                        : "+f"(c[mt][nt][0]), "+f"(c[mt][nt][1]),
                          "+f"(c[mt][nt][2]), "+f"(c[mt][nt][3])
                        : "r"(a[mt][0]), "r"(a[mt][1]), "r"(a[mt][2]), "r"(a[mt][3]),
                          "r"(b[nt][0]), "r"(b[nt][1]));
                }
        }
        __syncthreads();

        if (ck + 2 < DFEAT / BK) load_stage((ck + 2) % NSTAGE, (ck + 2) * BK);
    }

    // Epilogue -> bf16 P. C frag: c0 (g,2tg) c1 (g,2tg+1) c2 (g+8,2tg) c3 (g+8,2tg+1)
    #pragma unroll
    for (int mt = 0; mt < 4; mt++) {
        int row0 = rowBase + wm + mt * 16 + g;
        #pragma unroll
        for (int nt = 0; nt < 4; nt++) {
            int col = nBase + wn + nt * 8 + 2 * tg;
            if (row0 < M)
                *(__nv_bfloat162*)(g_P + (size_t)row0 * NCOLS + col) =
                    __float22bfloat162_rn(make_float2(c[mt][nt][0], c[mt][nt][1]));
            if (row0 + 8 < M)
                *(__nv_bfloat162*)(g_P + (size_t)(row0 + 8) * NCOLS + col) =
                    __float22bfloat162_rn(make_float2(c[mt][nt][2], c[mt][nt][3]));
        }
    }
}

// ------------- edge pass (proven, R11 verbatim): warp/edge, 2 in flight ------
__device__ __forceinline__ float edge_dot(uint4 uu, uint4 vv,
                                          const float* bb, const float* ww) {
    float acc = 0.f;
    const uint32_t* up = &uu.x;
    const uint32_t* vp = &vv.x;
    #pragma unroll
    for (int q = 0; q < 4; q++) {
        float2 uf = __bfloat1622float2(*(const __nv_bfloat162*)&up[q]);
        float2 vf = __bfloat1622float2(*(const __nv_bfloat162*)&vp[q]);
        float t;
        t = uf.x + vf.x + bb[2 * q];     if (t > 0.f) acc += t * ww[2 * q];
        t = uf.y + vf.y + bb[2 * q + 1]; if (t > 0.f) acc += t * ww[2 * q + 1];
    }
    return acc;
}

__global__ __launch_bounds__(256) void edge_mlp(
        const int* __restrict__ src, const int* __restrict__ dst,
        const float* __restrict__ b1, const float* __restrict__ W2,
        const float* __restrict__ b2, float* __restrict__ out, int E) {
    int tid = threadIdx.x;
    int lane = tid & 31;
    int gwarp = blockIdx.x * 8 + (tid >> 5);
    int nwarps = gridDim.x * 8;

    float bb[8], ww[8];
    #pragma unroll
    for (int i = 0; i < 8; i++) {
        bb[i] = __ldg(b1 + lane * 8 + i);
        ww[i] = __ldg(W2 + lane * 8 + i);
    }
    float bias2 = __ldg(b2);

    const __nv_bfloat16* P = g_P;
    for (int e = gwarp; e < E; e += 2 * nwarps) {
        int e2 = e + nwarps;
        bool have2 = e2 < E;
        int s0 = src[e], d0 = dst[e];
        int s1 = have2 ? src[e2] : 0;
        int d1 = have2 ? dst[e2] : 0;

        uint4 u0 = *(const uint4*)(P + (size_t)s0 * NCOLS + lane * 8);
        uint4 v0 = *(const uint4*)(P + (size_t)d0 * NCOLS + DFEAT + lane * 8);
        uint4 u1 = *(const uint4*)(P + (size_t)s1 * NCOLS + lane * 8);
        uint4 v1 = *(const uint4*)(P + (size_t)d1 * NCOLS + DFEAT + lane * 8);

        float a0 = edge_dot(u0, v0, bb, ww);
        float a1 = edge_dot(u1, v1, bb, ww);
        #pragma unroll
        for (int o = 16; o; o >>= 1) {
            a0 += __shfl_xor_sync(0xffffffffu, a0, o);
            a1 += __shfl_xor_sync(0xffffffffu, a1, o);
        }
        if (lane == 0) {
            out[e] = 1.f / (1.f + __expf(-(a0 + bias2)));
            if (have2) out[e2] = 1.f / (1.f + __expf(-(a1 + bias2)));
        }
    }
}

extern "C" void kernel_launch(void* const* d_in, const int* in_sizes, int n_in,
                              void* d_out, int out_size) {
    const float* h   = (const float*)d_in[0];
    const int*   src = (const int*)d_in[1];
    const int*   dst = (const int*)d_in[2];
    const float* W1  = (const float*)d_in[3];
    const float* b1  = (const float*)d_in[4];
    const float* W2  = (const float*)d_in[5];
    const float* b2  = (const float*)d_in[6];
    float* out = (float*)d_out;

    int M = in_sizes[0] / DFEAT;
    int E = in_sizes[1];

    prep_w<<<(NCOLS * DFEAT + 255) / 256, 256>>>(W1);
    {
        int n8 = M * DFEAT / 8;
        prep_h<<<(n8 + 255) / 256, 256>>>(h, M);
    }

    cudaFuncSetAttribute(gemm_bf16, cudaFuncAttributeMaxDynamicSharedMemorySize,
                         SMEM_BYTES);
    dim3 gg(NCOLS / BN, (M + BM - 1) / BM);   // x-fastest => A reuse in L2
    gemm_bf16<<<gg, 256, SMEM_BYTES>>>(M);

    edge_mlp<<<2368, 256>>>(src, dst, b1, W2, b2, out, E);
}